// round 6
// baseline (speedup 1.0000x reference)
#include <cuda_runtime.h>
#include <cstdint>
#include <cstddef>

#define B_    1024
#define N_    64
#define F_    1024
#define H1_   256
#define H2_   128
#define NC_   128
#define ALPHA_ 0.2f
#define EPS_  1e-5f

// ---------------- scratch (device globals; no allocations) ----------------
__device__ float g_nbh [B_ * N_ * H1_];   // 64 MB  layer-1 neighbor features
__device__ float g_nbh2[B_ * N_ * H2_];   // 32 MB  layer-2 neighbor features
__device__ float g_x1  [B_ * H1_];        // layer-1 attention output
__device__ float g_x2  [B_ * H2_];        // layer-2 attention output
__device__ float g_u1  [F_];              // W1^T a11
__device__ float g_u2  [H1_];             // W2^T a21
__device__ float g_c1;                    // b1 . a11
__device__ float g_c2;                    // b2 . a21
__device__ float g_cb  [B_];              // per-sample self score, layer 2
__device__ float g_nbmean[B_];            // per-sample BN stats for neighbors (layer1)
__device__ float g_nbrstd[B_];
__device__ float g_acc[4];                // global BN accumulators (sum,sumsq) x2
__device__ float g_bn1[2];                // mean, rstd for x-branch BN1
__device__ float g_bn2[2];                // mean, rstd for x-branch BN2

// ---------------- helpers ----------------
__device__ __forceinline__ float warpSum(float v) {
#pragma unroll
    for (int o = 16; o; o >>= 1) v += __shfl_down_sync(0xffffffffu, v, o);
    return v;
}

// valid on thread 0 only
__device__ __forceinline__ float blockReduce(float v, float* sbuf) {
    int lane = threadIdx.x & 31, warp = threadIdx.x >> 5;
    v = warpSum(v);
    __syncthreads();               // protect sbuf from any previous use
    if (lane == 0) sbuf[warp] = v;
    __syncthreads();
    float r = 0.f;
    int nw = blockDim.x >> 5;
    if (warp == 0) {
        r = (lane < nw) ? sbuf[lane] : 0.f;
        r = warpSum(r);
    }
    return r;
}

// packed f32x2 (FFMA2) helpers — only reachable via PTX on sm_103a
__device__ __forceinline__ unsigned long long pack2(float lo, float hi) {
    unsigned long long r;
    asm("mov.b64 %0, {%1, %2};" : "=l"(r) : "f"(lo), "f"(hi));
    return r;
}
__device__ __forceinline__ void fma2(unsigned long long& d, unsigned long long a,
                                     unsigned long long b) {
    asm("fma.rn.f32x2 %0, %1, %2, %0;" : "+l"(d) : "l"(a), "l"(b));
}
__device__ __forceinline__ float2 unpack2(unsigned long long v) {
    float2 r;
    asm("mov.b64 {%0, %1}, %2;" : "=f"(r.x), "=f"(r.y) : "l"(v));
    return r;
}

// ---------------- kernel 0: precompute u1,u2,c1,c2; zero accumulators ----------------
__global__ void __launch_bounds__(256) pre_kernel(
    const float* __restrict__ W1, const float* __restrict__ a11, const float* __restrict__ b1,
    const float* __restrict__ W2, const float* __restrict__ a21, const float* __restrict__ b2)
{
    int tid = threadIdx.x;
    __shared__ float s_red[32];
    if (blockIdx.x == 0) {
#pragma unroll
        for (int i = 0; i < 4; i++) {
            int f = tid + i * 256;
            float s = 0.f;
            for (int h = 0; h < H1_; h++) s += a11[h] * W1[(size_t)h * F_ + f];
            g_u1[f] = s;
        }
    } else if (blockIdx.x == 1) {
        float s = 0.f;
        for (int h = 0; h < H2_; h++) s += a21[h] * W2[(size_t)h * H1_ + tid];
        g_u2[tid] = s;
    } else {
        float p = b1[tid] * a11[tid];
        float S = blockReduce(p, s_red);
        if (tid == 0) g_c1 = S;
        float q = (tid < H2_) ? b2[tid] * a21[tid] : 0.f;
        float S2 = blockReduce(q, s_red);
        if (tid == 0) g_c2 = S2;
        if (tid < 4) g_acc[tid] = 0.f;
    }
}

// ---------------- tiled SGEMM with packed-f32x2 FMAs ----------------
// MODE 0: C = sign(A) @ W1^T + b1        (A = neighbor, K=1024, Ncol=256, C = g_nbh)
// MODE 1: C = bnrelu(g_nbh) @ W2^T + b2  (per-row-group BN,  K=256, Ncol=128, C = g_nbh2)
template <int MODE>
__global__ void __launch_bounds__(256) gemm_kernel(
    const float* __restrict__ A, const float* __restrict__ W, const float* __restrict__ bias,
    const float* __restrict__ gamma, const float* __restrict__ beta)
{
    const int K    = (MODE == 0) ? 1024 : 256;
    const int Ncol = (MODE == 0) ? 256 : 128;
    __shared__ float As[16][132];
    __shared__ float Bs[16][132];

    const int tid = threadIdx.x;
    const int tx = tid & 15, ty = tid >> 4;
    const int m0 = blockIdx.y * 128, n0 = blockIdx.x * 128;

    const float* Ap = (MODE == 0) ? A : g_nbh;
    float*       C  = (MODE == 0) ? g_nbh : g_nbh2;

    float g = 1.f, be = 0.f;
    if (MODE == 1) { g = *gamma; be = *beta; }

    unsigned long long acc2[8][4];
#pragma unroll
    for (int i = 0; i < 8; i++)
#pragma unroll
        for (int j = 0; j < 4; j++) acc2[i][j] = 0ull;

    for (int k0 = 0; k0 < K; k0 += 16) {
#pragma unroll
        for (int it = 0; it < 2; ++it) {
            int slot = tid + it * 256;
            int r = slot >> 2, cg = slot & 3;
            float4 v = *(const float4*)(Ap + (size_t)(m0 + r) * K + k0 + cg * 4);
            if (MODE == 0) {
                v.x /= fmaxf(fabsf(v.x), 1e-12f);
                v.y /= fmaxf(fabsf(v.y), 1e-12f);
                v.z /= fmaxf(fabsf(v.z), 1e-12f);
                v.w /= fmaxf(fabsf(v.w), 1e-12f);
            } else {
                int bb = (m0 + r) >> 6;
                float mn = g_nbmean[bb], rs = g_nbrstd[bb];
                v.x = fmaxf(g * (v.x - mn) * rs + be, 0.f);
                v.y = fmaxf(g * (v.y - mn) * rs + be, 0.f);
                v.z = fmaxf(g * (v.z - mn) * rs + be, 0.f);
                v.w = fmaxf(g * (v.w - mn) * rs + be, 0.f);
            }
            As[cg * 4 + 0][r] = v.x; As[cg * 4 + 1][r] = v.y;
            As[cg * 4 + 2][r] = v.z; As[cg * 4 + 3][r] = v.w;
        }
#pragma unroll
        for (int it = 0; it < 2; ++it) {
            int slot = tid + it * 256;
            int r = slot >> 2, cg = slot & 3;
            float4 v = *(const float4*)(W + (size_t)(n0 + r) * K + k0 + cg * 4);
            Bs[cg * 4 + 0][r] = v.x; Bs[cg * 4 + 1][r] = v.y;
            Bs[cg * 4 + 2][r] = v.z; Bs[cg * 4 + 3][r] = v.w;
        }
        __syncthreads();
#pragma unroll
        for (int k = 0; k < 16; k++) {
            float a[8], bq[8];
            *(float4*)&a[0]  = *(const float4*)&As[k][ty * 8];
            *(float4*)&a[4]  = *(const float4*)&As[k][ty * 8 + 4];
            *(float4*)&bq[0] = *(const float4*)&Bs[k][tx * 8];
            *(float4*)&bq[4] = *(const float4*)&Bs[k][tx * 8 + 4];
            unsigned long long bp[4];
#pragma unroll
            for (int j = 0; j < 4; j++) bp[j] = pack2(bq[2 * j], bq[2 * j + 1]);
#pragma unroll
            for (int i = 0; i < 8; i++) {
                unsigned long long as = pack2(a[i], a[i]);
#pragma unroll
                for (int j = 0; j < 4; j++) fma2(acc2[i][j], as, bp[j]);
            }
        }
        __syncthreads();
    }
#pragma unroll
    for (int i = 0; i < 8; i++) {
        size_t row = (size_t)(m0 + ty * 8 + i);
        float2* cp = (float2*)(C + row * Ncol + n0 + tx * 8);
#pragma unroll
        for (int j = 0; j < 4; j++) {
            float2 v = unpack2(acc2[i][j]);
            int col = n0 + tx * 8 + 2 * j;
            v.x += bias[col]; v.y += bias[col + 1];
            cp[j] = v;
        }
    }
}

// ---------------- attention layer 1 (+ per-b neighbor BN stats + global x1 stats) ----------
__global__ void __launch_bounds__(256) attn1_kernel(
    const float* __restrict__ x, const float* __restrict__ a12)
{
    int b = blockIdx.x, tid = threadIdx.x, lane = tid & 31, warp = tid >> 5;
    __shared__ float s_a12[256];
    __shared__ float s_sc[64];
    __shared__ float s_red[32];
    __shared__ float s_sx;

    s_a12[tid] = a12[tid];

    // self score: sign(x[b]) . u1 + c1
    float p = 0.f;
#pragma unroll
    for (int i = 0; i < 4; i++) {
        int f = tid + i * 256;
        float v = x[(size_t)b * F_ + f];
        v = v / fmaxf(fabsf(v), 1e-12f);
        p += v * g_u1[f];
    }
    float sx = blockReduce(p, s_red);
    if (tid == 0) s_sx = sx + g_c1;
    __syncthreads();

    const float* base = g_nbh + (size_t)b * N_ * H1_;
    float lsum = 0.f, lsq = 0.f;
#pragma unroll
    for (int nn = 0; nn < 8; nn++) {
        int n = warp * 8 + nn;
        const float* row = base + n * H1_;
        float d = 0.f;
#pragma unroll
        for (int i = 0; i < 8; i++) {
            int h = lane + 32 * i;
            float v = row[h];
            d += v * s_a12[h];
            lsum += v; lsq += v * v;
        }
        d = warpSum(d);
        if (lane == 0) s_sc[n] = d;
    }
    __syncthreads();

    if (warp == 0) {
        float c = s_sx;
        float v0 = c + s_sc[lane];      v0 = v0 > 0.f ? v0 : ALPHA_ * v0;
        float v1 = c + s_sc[lane + 32]; v1 = v1 > 0.f ? v1 : ALPHA_ * v1;
        float m = fmaxf(v0, v1);
#pragma unroll
        for (int o = 16; o; o >>= 1) m = fmaxf(m, __shfl_xor_sync(0xffffffffu, m, o));
        float e0 = expf(v0 - m), e1 = expf(v1 - m);
        float s = e0 + e1;
#pragma unroll
        for (int o = 16; o; o >>= 1) s += __shfl_xor_sync(0xffffffffu, s, o);
        float inv = 1.f / s;
        s_sc[lane] = e0 * inv; s_sc[lane + 32] = e1 * inv;
    }
    __syncthreads();

    float out = 0.f;
#pragma unroll
    for (int n = 0; n < N_; n++) out += s_sc[n] * base[n * H1_ + tid];
    g_x1[(size_t)b * H1_ + tid] = out;

    // per-sample BN stats over neighbors (N*H1 = 16384 elems)
    float S  = blockReduce(lsum, s_red);
    float S2 = blockReduce(lsq, s_red);
    if (tid == 0) {
        float mean = S * (1.f / 16384.f);
        float var  = S2 * (1.f / 16384.f) - mean * mean;
        g_nbmean[b] = mean;
        g_nbrstd[b] = rsqrtf(var + EPS_);
    }
    // global stats for x-branch BN1
    float So  = blockReduce(out, s_red);
    float So2 = blockReduce(out * out, s_red);
    if (tid == 0) { atomicAdd(&g_acc[0], So); atomicAdd(&g_acc[1], So2); }
}

__global__ void fin1_kernel() {
    if (threadIdx.x == 0) {
        float inv = 1.f / (float)(B_ * H1_);
        float m = g_acc[0] * inv;
        float var = g_acc[1] * inv - m * m;
        g_bn1[0] = m; g_bn1[1] = rsqrtf(var + EPS_);
    }
}

// self score layer 2: c_b = bnrelu(x1[b]) . u2 + c2
__global__ void __launch_bounds__(256) xc2_kernel(
    const float* __restrict__ g1p, const float* __restrict__ be1p)
{
    int b = blockIdx.x, tid = threadIdx.x;
    __shared__ float s_red[32];
    float g = *g1p, be = *be1p, mn = g_bn1[0], rs = g_bn1[1];
    float v = g_x1[(size_t)b * H1_ + tid];
    v = fmaxf(g * (v - mn) * rs + be, 0.f);
    float S = blockReduce(v * g_u2[tid], s_red);
    if (tid == 0) g_cb[b] = S + g_c2;
}

// ---------------- attention layer 2 (+ global x2 stats) ----------------
__global__ void __launch_bounds__(128) attn2_kernel(const float* __restrict__ a22)
{
    int b = blockIdx.x, tid = threadIdx.x, lane = tid & 31, warp = tid >> 5;
    __shared__ float s_a[128];
    __shared__ float s_sc[64];
    __shared__ float s_red[32];
    s_a[tid] = a22[tid];
    __syncthreads();

    const float* base = g_nbh2 + (size_t)b * N_ * H2_;
#pragma unroll
    for (int nn = 0; nn < 16; nn++) {
        int n = warp * 16 + nn;
        const float* row = base + n * H2_;
        float d = 0.f;
#pragma unroll
        for (int i = 0; i < 4; i++) { int h = lane + 32 * i; d += row[h] * s_a[h]; }
        d = warpSum(d);
        if (lane == 0) s_sc[n] = d;
    }
    __syncthreads();

    if (warp == 0) {
        float c = g_cb[b];
        float v0 = c + s_sc[lane];      v0 = v0 > 0.f ? v0 : ALPHA_ * v0;
        float v1 = c + s_sc[lane + 32]; v1 = v1 > 0.f ? v1 : ALPHA_ * v1;
        float m = fmaxf(v0, v1);
#pragma unroll
        for (int o = 16; o; o >>= 1) m = fmaxf(m, __shfl_xor_sync(0xffffffffu, m, o));
        float e0 = expf(v0 - m), e1 = expf(v1 - m);
        float s = e0 + e1;
#pragma unroll
        for (int o = 16; o; o >>= 1) s += __shfl_xor_sync(0xffffffffu, s, o);
        float inv = 1.f / s;
        s_sc[lane] = e0 * inv; s_sc[lane + 32] = e1 * inv;
    }
    __syncthreads();

    float out = 0.f;
#pragma unroll
    for (int n = 0; n < N_; n++) out += s_sc[n] * base[n * H2_ + tid];
    g_x2[(size_t)b * H2_ + tid] = out;

    float S  = blockReduce(out, s_red);
    float S2 = blockReduce(out * out, s_red);
    if (tid == 0) { atomicAdd(&g_acc[2], S); atomicAdd(&g_acc[3], S2); }
}

__global__ void fin2_kernel() {
    if (threadIdx.x == 0) {
        float inv = 1.f / (float)(B_ * H2_);
        float m = g_acc[2] * inv;
        float var = g_acc[3] * inv - m * m;
        g_bn2[0] = m; g_bn2[1] = rsqrtf(var + EPS_);
    }
}

// ---------------- final BN + classifier ----------------
__global__ void __launch_bounds__(128) logits_kernel(
    const float* __restrict__ Wl, const float* __restrict__ bl,
    const float* __restrict__ g2p, const float* __restrict__ be2p,
    float* __restrict__ out)
{
    int b = blockIdx.x, tid = threadIdx.x, lane = tid & 31, warp = tid >> 5;
    __shared__ float s_x[128];
    float g = *g2p, be = *be2p, mn = g_bn2[0], rs = g_bn2[1];
    float v = g_x2[(size_t)b * H2_ + tid];
    s_x[tid] = fmaxf(g * (v - mn) * rs + be, 0.f);
    __syncthreads();
    float4 xv = *(const float4*)&s_x[lane * 4];
#pragma unroll
    for (int cc = 0; cc < 32; cc++) {
        int c = warp * 32 + cc;
        float4 wv = *(const float4*)(Wl + (size_t)c * H2_ + lane * 4);
        float d = wv.x * xv.x + wv.y * xv.y + wv.z * xv.z + wv.w * xv.w;
        d = warpSum(d);
        if (lane == 0) out[(size_t)b * NC_ + c] = d + bl[c];
    }
}

// ---------------- launch ----------------
extern "C" void kernel_launch(void* const* d_in, const int* in_sizes, int n_in,
                              void* d_out, int out_size) {
    (void)in_sizes; (void)n_in; (void)out_size;
    const float* x   = (const float*)d_in[0];
    const float* nb  = (const float*)d_in[1];
    const float* W1  = (const float*)d_in[2];
    const float* b1  = (const float*)d_in[3];
    const float* a11 = (const float*)d_in[4];
    const float* a12 = (const float*)d_in[5];
    const float* g1  = (const float*)d_in[6];
    const float* be1 = (const float*)d_in[7];
    const float* W2  = (const float*)d_in[8];
    const float* b2  = (const float*)d_in[9];
    const float* a21 = (const float*)d_in[10];
    const float* a22 = (const float*)d_in[11];
    const float* g2  = (const float*)d_in[12];
    const float* be2 = (const float*)d_in[13];
    const float* Wl  = (const float*)d_in[14];
    const float* bl  = (const float*)d_in[15];
    float* out = (float*)d_out;

    pre_kernel<<<3, 256>>>(W1, a11, b1, W2, a21, b2);
    // layer-1 neighbor GEMM: [65536,1024] x [1024,256]
    gemm_kernel<0><<<dim3(2, 512), 256>>>(nb, W1, b1, nullptr, nullptr);
    attn1_kernel<<<B_, 256>>>(x, a12);
    fin1_kernel<<<1, 32>>>();
    xc2_kernel<<<B_, 256>>>(g1, be1);
    // layer-2 neighbor GEMM: bnrelu(nbh) [65536,256] x [256,128]
    gemm_kernel<1><<<dim3(1, 512), 256>>>(nullptr, W2, b2, g1, be1);
    attn2_kernel<<<B_, 128>>>(a22);
    fin2_kernel<<<1, 32>>>();
    logits_kernel<<<B_, 128>>>(Wl, bl, g2, be2, out);
}

// round 8
// speedup vs baseline: 2.6386x; 2.6386x over previous
#include <cuda_runtime.h>
#include <cuda_bf16.h>
#include <cstdint>
#include <cstddef>

#define B_    1024
#define N_    64
#define F_    1024
#define H1_   256
#define H2_   128
#define NC_   128
#define ALPHA_ 0.2f
#define EPS_  1e-5f

// ---------------- scratch (device globals; no allocations) ----------------
__device__ float g_nbh [B_ * N_ * H1_];   // 64 MB  layer-1 neighbor features
__device__ float g_nbh2[B_ * N_ * H2_];   // 32 MB  layer-2 neighbor features
__device__ float g_x1  [B_ * H1_];
__device__ float g_x2  [B_ * H2_];
__device__ float g_u1  [F_];
__device__ float g_u2  [H1_];
__device__ float g_c1;
__device__ float g_c2;
__device__ float g_cb  [B_];
__device__ float g_nbmean[B_];
__device__ float g_nbrstd[B_];
__device__ float g_acc[4];
__device__ float g_bn1[2];
__device__ float g_bn2[2];
// bf16 split of W1 (hi + lo), written by wsplit_kernel each launch
__device__ __align__(16) __nv_bfloat16 g_W1hi[H1_ * F_];
__device__ __align__(16) __nv_bfloat16 g_W1lo[H1_ * F_];

// ---------------- generic helpers ----------------
__device__ __forceinline__ float warpSum(float v) {
#pragma unroll
    for (int o = 16; o; o >>= 1) v += __shfl_down_sync(0xffffffffu, v, o);
    return v;
}
__device__ __forceinline__ float blockReduce(float v, float* sbuf) {
    int lane = threadIdx.x & 31, warp = threadIdx.x >> 5;
    v = warpSum(v);
    __syncthreads();
    if (lane == 0) sbuf[warp] = v;
    __syncthreads();
    float r = 0.f;
    int nw = blockDim.x >> 5;
    if (warp == 0) { r = (lane < nw) ? sbuf[lane] : 0.f; r = warpSum(r); }
    return r;
}

// packed f32x2 helpers (GEMM2 stays on the FMA pipe this round)
__device__ __forceinline__ unsigned long long pack2(float lo, float hi) {
    unsigned long long r;
    asm("mov.b64 %0, {%1, %2};" : "=l"(r) : "f"(lo), "f"(hi));
    return r;
}
__device__ __forceinline__ void fma2(unsigned long long& d, unsigned long long a,
                                     unsigned long long b) {
    asm("fma.rn.f32x2 %0, %1, %2, %0;" : "+l"(d) : "l"(a), "l"(b));
}
__device__ __forceinline__ float2 unpack2(unsigned long long v) {
    float2 r;
    asm("mov.b64 {%0, %1}, %2;" : "=f"(r.x), "=f"(r.y) : "l"(v));
    return r;
}

// ---------------- warp-MMA / async-copy wrappers (plain sm_80+ PTX only) ----------------
__device__ __forceinline__ uint32_t smem_u32(const void* p) {
    uint32_t a;
    asm("{ .reg .u64 t; cvta.to.shared.u64 t, %1; cvt.u32.u64 %0, t; }" : "=r"(a) : "l"(p));
    return a;
}
__device__ __forceinline__ uint32_t sw128(uint32_t x) { return x ^ ((x >> 3) & 0x70); }

__device__ __forceinline__ void cp16(uint32_t dst, const void* src) {
    asm volatile("cp.async.cg.shared.global [%0], [%1], 16;" :: "r"(dst), "l"(src));
}
__device__ __forceinline__ void cp_commit() {
    asm volatile("cp.async.commit_group;" ::: "memory");
}
__device__ __forceinline__ void cp_wait0() {
    asm volatile("cp.async.wait_group 0;" ::: "memory");
}
__device__ __forceinline__ void ldm_x4(uint32_t& r0, uint32_t& r1, uint32_t& r2,
                                       uint32_t& r3, uint32_t addr) {
    asm volatile("ldmatrix.sync.aligned.m8n8.x4.shared.b16 {%0,%1,%2,%3}, [%4];"
                 : "=r"(r0), "=r"(r1), "=r"(r2), "=r"(r3) : "r"(addr));
}
__device__ __forceinline__ void mma_bf16(float& d0, float& d1, float& d2, float& d3,
                                         uint32_t a0, uint32_t a1, uint32_t a2, uint32_t a3,
                                         uint32_t b0, uint32_t b1) {
    asm volatile(
        "mma.sync.aligned.m16n8k16.row.col.f32.bf16.bf16.f32 "
        "{%0,%1,%2,%3}, {%4,%5,%6,%7}, {%8,%9}, {%0,%1,%2,%3};"
        : "+f"(d0), "+f"(d1), "+f"(d2), "+f"(d3)
        : "r"(a0), "r"(a1), "r"(a2), "r"(a3), "r"(b0), "r"(b1));
}

// exact sign(v) matching v / max(|v|, 1e-12)
__device__ __forceinline__ float sgn_(float v) {
    float r = __int_as_float((__float_as_int(v) & 0x80000000u) | 0x3f800000u);
    return fabsf(v) >= 1e-12f ? r : v * 1e12f;
}

// ---------------- kernel 0: precompute u1,u2,c1,c2; zero accumulators ----------------
__global__ void __launch_bounds__(256) pre_kernel(
    const float* __restrict__ W1, const float* __restrict__ a11, const float* __restrict__ b1,
    const float* __restrict__ W2, const float* __restrict__ a21, const float* __restrict__ b2)
{
    int tid = threadIdx.x;
    __shared__ float s_red[32];
    if (blockIdx.x == 0) {
#pragma unroll
        for (int i = 0; i < 4; i++) {
            int f = tid + i * 256;
            float s = 0.f;
            for (int h = 0; h < H1_; h++) s += a11[h] * W1[(size_t)h * F_ + f];
            g_u1[f] = s;
        }
    } else if (blockIdx.x == 1) {
        float s = 0.f;
        for (int h = 0; h < H2_; h++) s += a21[h] * W2[(size_t)h * H1_ + tid];
        g_u2[tid] = s;
    } else {
        float p = b1[tid] * a11[tid];
        float S = blockReduce(p, s_red);
        if (tid == 0) g_c1 = S;
        float q = (tid < H2_) ? b2[tid] * a21[tid] : 0.f;
        float S2 = blockReduce(q, s_red);
        if (tid == 0) g_c2 = S2;
        if (tid < 4) g_acc[tid] = 0.f;
    }
}

// ---------------- split W1 into bf16 hi + lo ----------------
__global__ void __launch_bounds__(256) wsplit_kernel(const float* __restrict__ W1)
{
    int row = blockIdx.x;
    int t = threadIdx.x;
    float4 v = ((const float4*)(W1 + (size_t)row * F_))[t];
    __nv_bfloat16 h0 = __float2bfloat16(v.x);
    __nv_bfloat16 h1 = __float2bfloat16(v.y);
    __nv_bfloat16 h2 = __float2bfloat16(v.z);
    __nv_bfloat16 h3 = __float2bfloat16(v.w);
    __nv_bfloat16 l0 = __float2bfloat16(v.x - __bfloat162float(h0));
    __nv_bfloat16 l1 = __float2bfloat16(v.y - __bfloat162float(h1));
    __nv_bfloat16 l2 = __float2bfloat16(v.z - __bfloat162float(h2));
    __nv_bfloat16 l3 = __float2bfloat16(v.w - __bfloat162float(h3));
    __nv_bfloat162* dh = (__nv_bfloat162*)(g_W1hi + (size_t)row * F_ + t * 4);
    __nv_bfloat162* dl = (__nv_bfloat162*)(g_W1lo + (size_t)row * F_ + t * 4);
    dh[0] = __halves2bfloat162(h0, h1);
    dh[1] = __halves2bfloat162(h2, h3);
    dl[0] = __halves2bfloat162(l0, l1);
    dl[1] = __halves2bfloat162(l2, l3);
}

// ---------------- layer-1 GEMM on warp MMA (bf16 hi+lo, fp32 accum) ----------------
// C[65536,256] = sign(A)[65536,1024] @ (W1hi + W1lo)^T + b1
// CTA: M=128, N=256. 8 warps in 2(M) x 4(N): warp tile 64x64.
// K-chunk per iter = 64 bf16 (128B rows, SW128). 16 iters.
// SMEM: A[2][16KB] @ 0, B[2][hi 32KB | lo 32KB] @ 32KB. Total 160KB.
#define SM_TOTAL (32768 + 2 * 65536)

__global__ void __launch_bounds__(256, 1) tc_gemm1(const float* __restrict__ A,
                                                   const float* __restrict__ bias)
{
    extern __shared__ char smem[];
    const uint32_t sb = smem_u32(smem);
    const int tid = threadIdx.x, lane = tid & 31, wid = tid >> 5;
    const int m0 = blockIdx.x * 128;
    const int warp_m = wid >> 2, warp_n = wid & 3;

    const uint32_t offA0 = 0u, offA1 = 16384u;
    const uint32_t offB0 = 32768u, offB1 = 32768u + 65536u;

    float acc[4][8][4];
#pragma unroll
    for (int i = 0; i < 4; i++)
#pragma unroll
        for (int j = 0; j < 8; j++)
#pragma unroll
            for (int k = 0; k < 4; k++) acc[i][j][k] = 0.f;

    const float* Ag = A + (size_t)m0 * F_;
    // per-thread load coords
    const int ar = tid >> 4, ac4 = tid & 15;      // A: row (step 16), 4-float col group
    const int br = tid >> 3, bc = tid & 7;        // B: row (step 32), 16B col group

    float4 areg[8];
    // ---- prologue: LDG A(0); cp.async B(0) ----
#pragma unroll
    for (int i = 0; i < 8; i++)
        areg[i] = *(const float4*)(Ag + (size_t)(ar + i * 16) * F_ + ac4 * 4);
    {
        const __nv_bfloat16* Bh = g_W1hi;
        const __nv_bfloat16* Bl = g_W1lo;
#pragma unroll
        for (int i = 0; i < 8; i++) {
            int r = br + i * 32;
            uint32_t so = sw128((uint32_t)(r * 128 + bc * 16));
            cp16(sb + offB0 + so,         Bh + (size_t)r * F_ + bc * 8);
            cp16(sb + offB0 + 32768 + so, Bl + (size_t)r * F_ + bc * 8);
        }
        cp_commit();
    }

    for (int it = 0; it < 16; ++it) {
        const int s = it & 1;
        const uint32_t aOff = s ? offA1 : offA0;
        const uint32_t bOff = s ? offB1 : offB0;

        // 1. STS A(it): convert to sign bf16, swizzled
#pragma unroll
        for (int i = 0; i < 8; i++) {
            float4 v = areg[i];
            __nv_bfloat162 p0 = __halves2bfloat162(__float2bfloat16(sgn_(v.x)),
                                                   __float2bfloat16(sgn_(v.y)));
            __nv_bfloat162 p1 = __halves2bfloat162(__float2bfloat16(sgn_(v.z)),
                                                   __float2bfloat16(sgn_(v.w)));
            uint2 st; st.x = *(uint32_t*)&p0; st.y = *(uint32_t*)&p1;
            *(uint2*)(smem + aOff + sw128((uint32_t)((ar + i * 16) * 128 + ac4 * 8))) = st;
        }
        // 2. LDG A(it+1)
        if (it + 1 < 16) {
            int k0 = (it + 1) * 64;
#pragma unroll
            for (int i = 0; i < 8; i++)
                areg[i] = *(const float4*)(Ag + (size_t)(ar + i * 16) * F_ + k0 + ac4 * 4);
        }
        // 3. B(it) complete
        cp_wait0();
        // 4. publish
        __syncthreads();
        // 5. prefetch B(it+1) (safe after barrier: MMA(it-1) on the target buf is done)
        if (it + 1 < 16) {
            int k0 = (it + 1) * 64;
            uint32_t bN = s ? offB0 : offB1;
#pragma unroll
            for (int i = 0; i < 8; i++) {
                int r = br + i * 32;
                uint32_t so = sw128((uint32_t)(r * 128 + bc * 16));
                cp16(sb + bN + so,         g_W1hi + (size_t)r * F_ + k0 + bc * 8);
                cp16(sb + bN + 32768 + so, g_W1lo + (size_t)r * F_ + k0 + bc * 8);
            }
            cp_commit();
        }
        // 6. MMAs on stage s
        const int mrow = warp_m * 64 + (lane & 15);
        const int nrow = warp_n * 64 + (lane & 7) + ((lane & 16) >> 1);
        const int kbA = ((lane >> 4) & 1) * 16;
        const int kbB = ((lane >> 3) & 1) * 16;
#pragma unroll
        for (int kk = 0; kk < 4; kk++) {
            uint32_t a[4][4];
#pragma unroll
            for (int mt = 0; mt < 4; mt++)
                ldm_x4(a[mt][0], a[mt][1], a[mt][2], a[mt][3],
                       sb + aOff + sw128((uint32_t)((mrow + mt * 16) * 128 + kk * 32 + kbA)));
#pragma unroll
            for (int half = 0; half < 2; half++) {
                uint32_t bb = sb + bOff + half * 32768;
#pragma unroll
                for (int np = 0; np < 4; np++) {
                    uint32_t b0, b1, b2, b3;
                    ldm_x4(b0, b1, b2, b3,
                           bb + sw128((uint32_t)((nrow + np * 16) * 128 + kk * 32 + kbB)));
#pragma unroll
                    for (int mt = 0; mt < 4; mt++) {
                        mma_bf16(acc[mt][2 * np][0], acc[mt][2 * np][1],
                                 acc[mt][2 * np][2], acc[mt][2 * np][3],
                                 a[mt][0], a[mt][1], a[mt][2], a[mt][3], b0, b1);
                        mma_bf16(acc[mt][2 * np + 1][0], acc[mt][2 * np + 1][1],
                                 acc[mt][2 * np + 1][2], acc[mt][2 * np + 1][3],
                                 a[mt][0], a[mt][1], a[mt][2], a[mt][3], b2, b3);
                    }
                }
            }
        }
    }

    // ---- epilogue: bias + store ----
#pragma unroll
    for (int mt = 0; mt < 4; mt++) {
        int r0 = m0 + warp_m * 64 + mt * 16 + (lane >> 2);
        float* C0 = g_nbh + (size_t)r0 * H1_;
        float* C1 = C0 + 8 * H1_;
#pragma unroll
        for (int nt = 0; nt < 8; nt++) {
            int col = warp_n * 64 + nt * 8 + (lane & 3) * 2;
            float2 bv = *(const float2*)(bias + col);
            float2 o0, o1;
            o0.x = acc[mt][nt][0] + bv.x; o0.y = acc[mt][nt][1] + bv.y;
            o1.x = acc[mt][nt][2] + bv.x; o1.y = acc[mt][nt][3] + bv.y;
            *(float2*)(C0 + col) = o0;
            *(float2*)(C1 + col) = o1;
        }
    }
}

// ---------------- layer-2 GEMM (f32x2 FMA path) ----------------
__global__ void __launch_bounds__(256) gemm2_kernel(
    const float* __restrict__ W, const float* __restrict__ bias,
    const float* __restrict__ gamma, const float* __restrict__ beta)
{
    const int K = 256, Ncol = 128;
    __shared__ float As[16][132];
    __shared__ float Bs[16][132];

    const int tid = threadIdx.x;
    const int tx = tid & 15, ty = tid >> 4;
    const int m0 = blockIdx.y * 128, n0 = blockIdx.x * 128;

    float g = *gamma, be = *beta;

    unsigned long long acc2[8][4];
#pragma unroll
    for (int i = 0; i < 8; i++)
#pragma unroll
        for (int j = 0; j < 4; j++) acc2[i][j] = 0ull;

    for (int k0 = 0; k0 < K; k0 += 16) {
#pragma unroll
        for (int it = 0; it < 2; ++it) {
            int slot = tid + it * 256;
            int r = slot >> 2, cg = slot & 3;
            float4 v = *(const float4*)(g_nbh + (size_t)(m0 + r) * K + k0 + cg * 4);
            int bb = (m0 + r) >> 6;
            float mn = g_nbmean[bb], rs = g_nbrstd[bb];
            v.x = fmaxf(g * (v.x - mn) * rs + be, 0.f);
            v.y = fmaxf(g * (v.y - mn) * rs + be, 0.f);
            v.z = fmaxf(g * (v.z - mn) * rs + be, 0.f);
            v.w = fmaxf(g * (v.w - mn) * rs + be, 0.f);
            As[cg * 4 + 0][r] = v.x; As[cg * 4 + 1][r] = v.y;
            As[cg * 4 + 2][r] = v.z; As[cg * 4 + 3][r] = v.w;
        }
#pragma unroll
        for (int it = 0; it < 2; ++it) {
            int slot = tid + it * 256;
            int r = slot >> 2, cg = slot & 3;
            float4 v = *(const float4*)(W + (size_t)(n0 + r) * K + k0 + cg * 4);
            Bs[cg * 4 + 0][r] = v.x; Bs[cg * 4 + 1][r] = v.y;
            Bs[cg * 4 + 2][r] = v.z; Bs[cg * 4 + 3][r] = v.w;
        }
        __syncthreads();
#pragma unroll
        for (int k = 0; k < 16; k++) {
            float a[8], bq[8];
            *(float4*)&a[0]  = *(const float4*)&As[k][ty * 8];
            *(float4*)&a[4]  = *(const float4*)&As[k][ty * 8 + 4];
            *(float4*)&bq[0] = *(const float4*)&Bs[k][tx * 8];
            *(float4*)&bq[4] = *(const float4*)&Bs[k][tx * 8 + 4];
            unsigned long long bp[4];
#pragma unroll
            for (int j = 0; j < 4; j++) bp[j] = pack2(bq[2 * j], bq[2 * j + 1]);
#pragma unroll
            for (int i = 0; i < 8; i++) {
                unsigned long long as = pack2(a[i], a[i]);
#pragma unroll
                for (int j = 0; j < 4; j++) fma2(acc2[i][j], as, bp[j]);
            }
        }
        __syncthreads();
    }
#pragma unroll
    for (int i = 0; i < 8; i++) {
        size_t row = (size_t)(m0 + ty * 8 + i);
        float2* cp = (float2*)(g_nbh2 + row * Ncol + n0 + tx * 8);
#pragma unroll
        for (int j = 0; j < 4; j++) {
            float2 v = unpack2(acc2[i][j]);
            int col = n0 + tx * 8 + 2 * j;
            v.x += bias[col]; v.y += bias[col + 1];
            cp[j] = v;
        }
    }
}

// ---------------- attention layer 1 ----------------
__global__ void __launch_bounds__(256) attn1_kernel(
    const float* __restrict__ x, const float* __restrict__ a12)
{
    int b = blockIdx.x, tid = threadIdx.x, lane = tid & 31, warp = tid >> 5;
    __shared__ float s_a12[256];
    __shared__ float s_sc[64];
    __shared__ float s_red[32];
    __shared__ float s_sx;

    s_a12[tid] = a12[tid];

    float p = 0.f;
#pragma unroll
    for (int i = 0; i < 4; i++) {
        int f = tid + i * 256;
        float v = x[(size_t)b * F_ + f];
        v = v / fmaxf(fabsf(v), 1e-12f);
        p += v * g_u1[f];
    }
    float sx = blockReduce(p, s_red);
    if (tid == 0) s_sx = sx + g_c1;
    __syncthreads();

    const float* base = g_nbh + (size_t)b * N_ * H1_;
    float lsum = 0.f, lsq = 0.f;
#pragma unroll
    for (int nn = 0; nn < 8; nn++) {
        int n = warp * 8 + nn;
        const float* row = base + n * H1_;
        float d = 0.f;
#pragma unroll
        for (int i = 0; i < 8; i++) {
            int h = lane + 32 * i;
            float v = row[h];
            d += v * s_a12[h];
            lsum += v; lsq += v * v;
        }
        d = warpSum(d);
        if (lane == 0) s_sc[n] = d;
    }
    __syncthreads();

    if (warp == 0) {
        float c = s_sx;
        float v0 = c + s_sc[lane];      v0 = v0 > 0.f ? v0 : ALPHA_ * v0;
        float v1 = c + s_sc[lane + 32]; v1 = v1 > 0.f ? v1 : ALPHA_ * v1;
        float m = fmaxf(v0, v1);
#pragma unroll
        for (int o = 16; o; o >>= 1) m = fmaxf(m, __shfl_xor_sync(0xffffffffu, m, o));
        float e0 = expf(v0 - m), e1 = expf(v1 - m);
        float s = e0 + e1;
#pragma unroll
        for (int o = 16; o; o >>= 1) s += __shfl_xor_sync(0xffffffffu, s, o);
        float inv = 1.f / s;
        s_sc[lane] = e0 * inv; s_sc[lane + 32] = e1 * inv;
    }
    __syncthreads();

    float out = 0.f;
#pragma unroll
    for (int n = 0; n < N_; n++) out += s_sc[n] * base[n * H1_ + tid];
    g_x1[(size_t)b * H1_ + tid] = out;

    float S  = blockReduce(lsum, s_red);
    float S2 = blockReduce(lsq, s_red);
    if (tid == 0) {
        float mean = S * (1.f / 16384.f);
        float var  = S2 * (1.f / 16384.f) - mean * mean;
        g_nbmean[b] = mean;
        g_nbrstd[b] = rsqrtf(var + EPS_);
    }
    float So  = blockReduce(out, s_red);
    float So2 = blockReduce(out * out, s_red);
    if (tid == 0) { atomicAdd(&g_acc[0], So); atomicAdd(&g_acc[1], So2); }
}

__global__ void fin1_kernel() {
    if (threadIdx.x == 0) {
        float inv = 1.f / (float)(B_ * H1_);
        float m = g_acc[0] * inv;
        float var = g_acc[1] * inv - m * m;
        g_bn1[0] = m; g_bn1[1] = rsqrtf(var + EPS_);
    }
}

__global__ void __launch_bounds__(256) xc2_kernel(
    const float* __restrict__ g1p, const float* __restrict__ be1p)
{
    int b = blockIdx.x, tid = threadIdx.x;
    __shared__ float s_red[32];
    float g = *g1p, be = *be1p, mn = g_bn1[0], rs = g_bn1[1];
    float v = g_x1[(size_t)b * H1_ + tid];
    v = fmaxf(g * (v - mn) * rs + be, 0.f);
    float S = blockReduce(v * g_u2[tid], s_red);
    if (tid == 0) g_cb[b] = S + g_c2;
}

// ---------------- attention layer 2 ----------------
__global__ void __launch_bounds__(128) attn2_kernel(const float* __restrict__ a22)
{
    int b = blockIdx.x, tid = threadIdx.x, lane = tid & 31, warp = tid >> 5;
    __shared__ float s_a[128];
    __shared__ float s_sc[64];
    __shared__ float s_red[32];
    s_a[tid] = a22[tid];
    __syncthreads();

    const float* base = g_nbh2 + (size_t)b * N_ * H2_;
#pragma unroll
    for (int nn = 0; nn < 16; nn++) {
        int n = warp * 16 + nn;
        const float* row = base + n * H2_;
        float d = 0.f;
#pragma unroll
        for (int i = 0; i < 4; i++) { int h = lane + 32 * i; d += row[h] * s_a[h]; }
        d = warpSum(d);
        if (lane == 0) s_sc[n] = d;
    }
    __syncthreads();

    if (warp == 0) {
        float c = g_cb[b];
        float v0 = c + s_sc[lane];      v0 = v0 > 0.f ? v0 : ALPHA_ * v0;
        float v1 = c + s_sc[lane + 32]; v1 = v1 > 0.f ? v1 : ALPHA_ * v1;
        float m = fmaxf(v0, v1);
#pragma unroll
        for (int o = 16; o; o >>= 1) m = fmaxf(m, __shfl_xor_sync(0xffffffffu, m, o));
        float e0 = expf(v0 - m), e1 = expf(v1 - m);
        float s = e0 + e1;
#pragma unroll
        for (int o = 16; o; o >>= 1) s += __shfl_xor_sync(0xffffffffu, s, o);
        float inv = 1.f / s;
        s_sc[lane] = e0 * inv; s_sc[lane + 32] = e1 * inv;
    }
    __syncthreads();

    float out = 0.f;
#pragma unroll
    for (int n = 0; n < N_; n++) out += s_sc[n] * base[n * H2_ + tid];
    g_x2[(size_t)b * H2_ + tid] = out;

    float S  = blockReduce(out, s_red);
    float S2 = blockReduce(out * out, s_red);
    if (tid == 0) { atomicAdd(&g_acc[2], S); atomicAdd(&g_acc[3], S2); }
}

__global__ void fin2_kernel() {
    if (threadIdx.x == 0) {
        float inv = 1.f / (float)(B_ * H2_);
        float m = g_acc[2] * inv;
        float var = g_acc[3] * inv - m * m;
        g_bn2[0] = m; g_bn2[1] = rsqrtf(var + EPS_);
    }
}

// ---------------- final BN + classifier ----------------
__global__ void __launch_bounds__(128) logits_kernel(
    const float* __restrict__ Wl, const float* __restrict__ bl,
    const float* __restrict__ g2p, const float* __restrict__ be2p,
    float* __restrict__ out)
{
    int b = blockIdx.x, tid = threadIdx.x, lane = tid & 31, warp = tid >> 5;
    __shared__ float s_x[128];
    float g = *g2p, be = *be2p, mn = g_bn2[0], rs = g_bn2[1];
    float v = g_x2[(size_t)b * H2_ + tid];
    s_x[tid] = fmaxf(g * (v - mn) * rs + be, 0.f);
    __syncthreads();
    float4 xv = *(const float4*)&s_x[lane * 4];
#pragma unroll
    for (int cc = 0; cc < 32; cc++) {
        int c = warp * 32 + cc;
        float4 wv = *(const float4*)(Wl + (size_t)c * H2_ + lane * 4);
        float d = wv.x * xv.x + wv.y * xv.y + wv.z * xv.z + wv.w * xv.w;
        d = warpSum(d);
        if (lane == 0) out[(size_t)b * NC_ + c] = d + bl[c];
    }
}

// ---------------- launch ----------------
extern "C" void kernel_launch(void* const* d_in, const int* in_sizes, int n_in,
                              void* d_out, int out_size) {
    (void)in_sizes; (void)n_in; (void)out_size;
    const float* x   = (const float*)d_in[0];
    const float* nb  = (const float*)d_in[1];
    const float* W1  = (const float*)d_in[2];
    const float* b1  = (const float*)d_in[3];
    const float* a11 = (const float*)d_in[4];
    const float* a12 = (const float*)d_in[5];
    const float* g1  = (const float*)d_in[6];
    const float* be1 = (const float*)d_in[7];
    const float* W2  = (const float*)d_in[8];
    const float* b2  = (const float*)d_in[9];
    const float* a21 = (const float*)d_in[10];
    const float* a22 = (const float*)d_in[11];
    const float* g2  = (const float*)d_in[12];
    const float* be2 = (const float*)d_in[13];
    const float* Wl  = (const float*)d_in[14];
    const float* bl  = (const float*)d_in[15];
    float* out = (float*)d_out;

    cudaFuncSetAttribute(tc_gemm1, cudaFuncAttributeMaxDynamicSharedMemorySize, SM_TOTAL);

    pre_kernel<<<3, 256>>>(W1, a11, b1, W2, a21, b2);
    wsplit_kernel<<<H1_, 256>>>(W1);
    tc_gemm1<<<512, 256, SM_TOTAL>>>(nb, b1);
    attn1_kernel<<<B_, 256>>>(x, a12);
    fin1_kernel<<<1, 32>>>();
    xc2_kernel<<<B_, 256>>>(g1, be1);
    gemm2_kernel<<<dim3(1, 512), 256>>>(W2, b2, g1, be1);
    attn2_kernel<<<B_, 128>>>(a22);
    fin2_kernel<<<1, 32>>>();
    logits_kernel<<<B_, 128>>>(Wl, bl, g2, be2, out);
}

// round 12
// speedup vs baseline: 3.9870x; 1.5110x over previous
#include <cuda_runtime.h>
#include <cuda_bf16.h>
#include <cstdint>
#include <cstddef>

#define B_    1024
#define N_    64
#define F_    1024
#define H1_   256
#define H2_   128
#define NC_   128
#define ALPHA_ 0.2f
#define EPS_  1e-5f

// ---------------- scratch (device globals; no allocations) ----------------
__device__ float g_nbh [B_ * N_ * H1_];   // 64 MB  layer-1 neighbor features
__device__ float g_x1  [B_ * H1_];
__device__ float g_x2  [B_ * H2_];
__device__ float g_u1  [F_];              // W1^T a11
__device__ float g_u2  [H1_];             // W2^T a21  (self branch, layer 2)
__device__ float g_u2b [H1_];             // W2^T a22  (neighbor branch, layer 2)
__device__ float g_c1;                    // b1 . a11
__device__ float g_c2;                    // b2 . a21
__device__ float g_c2b;                   // b2 . a22
__device__ float g_nbmean[B_];            // per-sample BN stats of layer-1 neighbors
__device__ float g_nbrstd[B_];
__device__ float g_acc[4];                // (sum,sumsq) for x1 ; (sum,sumsq) for x2
// bf16 split of W1 (hi + lo)
__device__ __align__(16) __nv_bfloat16 g_W1hi[H1_ * F_];
__device__ __align__(16) __nv_bfloat16 g_W1lo[H1_ * F_];

// ---------------- generic helpers ----------------
__device__ __forceinline__ float warpSum(float v) {
#pragma unroll
    for (int o = 16; o; o >>= 1) v += __shfl_down_sync(0xffffffffu, v, o);
    return v;
}
__device__ __forceinline__ float blockReduce(float v, float* sbuf) {
    int lane = threadIdx.x & 31, warp = threadIdx.x >> 5;
    v = warpSum(v);
    __syncthreads();
    if (lane == 0) sbuf[warp] = v;
    __syncthreads();
    float r = 0.f;
    int nw = blockDim.x >> 5;
    if (warp == 0) { r = (lane < nw) ? sbuf[lane] : 0.f; r = warpSum(r); }
    return r;
}

// ---------------- warp-MMA / async-copy wrappers (plain sm_80+ PTX only) ----------------
__device__ __forceinline__ uint32_t smem_u32(const void* p) {
    uint32_t a;
    asm("{ .reg .u64 t; cvta.to.shared.u64 t, %1; cvt.u32.u64 %0, t; }" : "=r"(a) : "l"(p));
    return a;
}
__device__ __forceinline__ uint32_t sw128(uint32_t x) { return x ^ ((x >> 3) & 0x70); }

__device__ __forceinline__ void cp16(uint32_t dst, const void* src) {
    asm volatile("cp.async.cg.shared.global [%0], [%1], 16;" :: "r"(dst), "l"(src));
}
__device__ __forceinline__ void cp_commit() {
    asm volatile("cp.async.commit_group;" ::: "memory");
}
__device__ __forceinline__ void cp_wait0() {
    asm volatile("cp.async.wait_group 0;" ::: "memory");
}
__device__ __forceinline__ void ldm_x4(uint32_t& r0, uint32_t& r1, uint32_t& r2,
                                       uint32_t& r3, uint32_t addr) {
    asm volatile("ldmatrix.sync.aligned.m8n8.x4.shared.b16 {%0,%1,%2,%3}, [%4];"
                 : "=r"(r0), "=r"(r1), "=r"(r2), "=r"(r3) : "r"(addr));
}
__device__ __forceinline__ void mma_bf16(float& d0, float& d1, float& d2, float& d3,
                                         uint32_t a0, uint32_t a1, uint32_t a2, uint32_t a3,
                                         uint32_t b0, uint32_t b1) {
    asm volatile(
        "mma.sync.aligned.m16n8k16.row.col.f32.bf16.bf16.f32 "
        "{%0,%1,%2,%3}, {%4,%5,%6,%7}, {%8,%9}, {%0,%1,%2,%3};"
        : "+f"(d0), "+f"(d1), "+f"(d2), "+f"(d3)
        : "r"(a0), "r"(a1), "r"(a2), "r"(a3), "r"(b0), "r"(b1));
}

// exact sign(v) matching v / max(|v|, 1e-12)
__device__ __forceinline__ float sgn_(float v) {
    float r = __int_as_float((__float_as_int(v) & 0x80000000u) | 0x3f800000u);
    return fabsf(v) >= 1e-12f ? r : v * 1e12f;
}

// ---------------- kernel 0: precompute u1,u2,u2b,c1,c2,c2b; zero accumulators ----------
__global__ void __launch_bounds__(256) pre_kernel(
    const float* __restrict__ W1, const float* __restrict__ a11, const float* __restrict__ b1,
    const float* __restrict__ W2, const float* __restrict__ a21, const float* __restrict__ a22,
    const float* __restrict__ b2)
{
    int tid = threadIdx.x, bid = blockIdx.x;
    __shared__ float s_a[256];
    __shared__ float s_red[32];
    if (bid < 4) {
        s_a[tid] = a11[tid];
        __syncthreads();
        int f = bid * 256 + tid;
        float s0 = 0.f, s1 = 0.f, s2 = 0.f, s3 = 0.f;
#pragma unroll 4
        for (int h = 0; h < H1_; h += 4) {
            s0 += s_a[h]     * W1[(size_t)h * F_ + f];
            s1 += s_a[h + 1] * W1[(size_t)(h + 1) * F_ + f];
            s2 += s_a[h + 2] * W1[(size_t)(h + 2) * F_ + f];
            s3 += s_a[h + 3] * W1[(size_t)(h + 3) * F_ + f];
        }
        g_u1[f] = (s0 + s1) + (s2 + s3);
    } else if (bid == 4) {
        if (tid < 128) s_a[tid] = a21[tid];
        else s_a[tid] = a22[tid - 128];
        __syncthreads();
        int h = tid;
        float p0 = 0.f, p1 = 0.f, q0 = 0.f, q1 = 0.f;
#pragma unroll 4
        for (int c = 0; c < H2_; c += 2) {
            float w0 = W2[(size_t)c * H1_ + h];
            float w1 = W2[(size_t)(c + 1) * H1_ + h];
            p0 += s_a[c] * w0;       p1 += s_a[c + 1] * w1;
            q0 += s_a[128 + c] * w0; q1 += s_a[128 + c + 1] * w1;
        }
        g_u2[h]  = p0 + p1;
        g_u2b[h] = q0 + q1;
    } else {
        float p = b1[tid] * a11[tid];
        float S = blockReduce(p, s_red);
        if (tid == 0) g_c1 = S;
        float q = (tid < H2_) ? b2[tid] * a21[tid] : 0.f;
        float S2 = blockReduce(q, s_red);
        if (tid == 0) g_c2 = S2;
        float r = (tid < H2_) ? b2[tid] * a22[tid] : 0.f;
        float S3 = blockReduce(r, s_red);
        if (tid == 0) g_c2b = S3;
        if (tid < 4) g_acc[tid] = 0.f;
    }
}

// ---------------- split W1 into bf16 hi + lo ----------------
__global__ void __launch_bounds__(256) wsplit_kernel(const float* __restrict__ W1)
{
    int row = blockIdx.x;
    int t = threadIdx.x;
    float4 v = ((const float4*)(W1 + (size_t)row * F_))[t];
    __nv_bfloat16 h0 = __float2bfloat16(v.x);
    __nv_bfloat16 h1 = __float2bfloat16(v.y);
    __nv_bfloat16 h2 = __float2bfloat16(v.z);
    __nv_bfloat16 h3 = __float2bfloat16(v.w);
    __nv_bfloat16 l0 = __float2bfloat16(v.x - __bfloat162float(h0));
    __nv_bfloat16 l1 = __float2bfloat16(v.y - __bfloat162float(h1));
    __nv_bfloat16 l2 = __float2bfloat16(v.z - __bfloat162float(h2));
    __nv_bfloat16 l3 = __float2bfloat16(v.w - __bfloat162float(h3));
    __nv_bfloat162* dh = (__nv_bfloat162*)(g_W1hi + (size_t)row * F_ + t * 4);
    __nv_bfloat162* dl = (__nv_bfloat162*)(g_W1lo + (size_t)row * F_ + t * 4);
    dh[0] = __halves2bfloat162(h0, h1);
    dh[1] = __halves2bfloat162(h2, h3);
    dl[0] = __halves2bfloat162(l0, l1);
    dl[1] = __halves2bfloat162(l2, l3);
}

// ---------------- layer-1 GEMM on warp MMA (bf16 hi+lo, fp32 accum) ----------------
#define SM_TOTAL (32768 + 2 * 65536)

__global__ void __launch_bounds__(256, 1) tc_gemm1(const float* __restrict__ A,
                                                   const float* __restrict__ bias)
{
    extern __shared__ char smem[];
    const uint32_t sb = smem_u32(smem);
    const int tid = threadIdx.x, lane = tid & 31, wid = tid >> 5;
    const int m0 = blockIdx.x * 128;
    const int warp_m = wid >> 2, warp_n = wid & 3;

    const uint32_t offA0 = 0u, offA1 = 16384u;
    const uint32_t offB0 = 32768u, offB1 = 32768u + 65536u;

    float acc[4][8][4];
#pragma unroll
    for (int i = 0; i < 4; i++)
#pragma unroll
        for (int j = 0; j < 8; j++)
#pragma unroll
            for (int k = 0; k < 4; k++) acc[i][j][k] = 0.f;

    const float* Ag = A + (size_t)m0 * F_;
    const int ar = tid >> 4, ac4 = tid & 15;
    const int br = tid >> 3, bc = tid & 7;

    float4 areg[8];
#pragma unroll
    for (int i = 0; i < 8; i++)
        areg[i] = *(const float4*)(Ag + (size_t)(ar + i * 16) * F_ + ac4 * 4);
    {
#pragma unroll
        for (int i = 0; i < 8; i++) {
            int r = br + i * 32;
            uint32_t so = sw128((uint32_t)(r * 128 + bc * 16));
            cp16(sb + offB0 + so,         g_W1hi + (size_t)r * F_ + bc * 8);
            cp16(sb + offB0 + 32768 + so, g_W1lo + (size_t)r * F_ + bc * 8);
        }
        cp_commit();
    }

    for (int it = 0; it < 16; ++it) {
        const int s = it & 1;
        const uint32_t aOff = s ? offA1 : offA0;
        const uint32_t bOff = s ? offB1 : offB0;

#pragma unroll
        for (int i = 0; i < 8; i++) {
            float4 v = areg[i];
            __nv_bfloat162 p0 = __halves2bfloat162(__float2bfloat16(sgn_(v.x)),
                                                   __float2bfloat16(sgn_(v.y)));
            __nv_bfloat162 p1 = __halves2bfloat162(__float2bfloat16(sgn_(v.z)),
                                                   __float2bfloat16(sgn_(v.w)));
            uint2 st; st.x = *(uint32_t*)&p0; st.y = *(uint32_t*)&p1;
            *(uint2*)(smem + aOff + sw128((uint32_t)((ar + i * 16) * 128 + ac4 * 8))) = st;
        }
        if (it + 1 < 16) {
            int k0 = (it + 1) * 64;
#pragma unroll
            for (int i = 0; i < 8; i++)
                areg[i] = *(const float4*)(Ag + (size_t)(ar + i * 16) * F_ + k0 + ac4 * 4);
        }
        cp_wait0();
        __syncthreads();
        if (it + 1 < 16) {
            int k0 = (it + 1) * 64;
            uint32_t bN = s ? offB0 : offB1;
#pragma unroll
            for (int i = 0; i < 8; i++) {
                int r = br + i * 32;
                uint32_t so = sw128((uint32_t)(r * 128 + bc * 16));
                cp16(sb + bN + so,         g_W1hi + (size_t)r * F_ + k0 + bc * 8);
                cp16(sb + bN + 32768 + so, g_W1lo + (size_t)r * F_ + k0 + bc * 8);
            }
            cp_commit();
        }
        const int mrow = warp_m * 64 + (lane & 15);
        const int nrow = warp_n * 64 + (lane & 7) + ((lane & 16) >> 1);
        const int kbA = ((lane >> 4) & 1) * 16;
        const int kbB = ((lane >> 3) & 1) * 16;
#pragma unroll
        for (int kk = 0; kk < 4; kk++) {
            uint32_t a[4][4];
#pragma unroll
            for (int mt = 0; mt < 4; mt++)
                ldm_x4(a[mt][0], a[mt][1], a[mt][2], a[mt][3],
                       sb + aOff + sw128((uint32_t)((mrow + mt * 16) * 128 + kk * 32 + kbA)));
#pragma unroll
            for (int half = 0; half < 2; half++) {
                uint32_t bb = sb + bOff + half * 32768;
#pragma unroll
                for (int np = 0; np < 4; np++) {
                    uint32_t b0, b1, b2, b3;
                    ldm_x4(b0, b1, b2, b3,
                           bb + sw128((uint32_t)((nrow + np * 16) * 128 + kk * 32 + kbB)));
#pragma unroll
                    for (int mt = 0; mt < 4; mt++) {
                        mma_bf16(acc[mt][2 * np][0], acc[mt][2 * np][1],
                                 acc[mt][2 * np][2], acc[mt][2 * np][3],
                                 a[mt][0], a[mt][1], a[mt][2], a[mt][3], b0, b1);
                        mma_bf16(acc[mt][2 * np + 1][0], acc[mt][2 * np + 1][1],
                                 acc[mt][2 * np + 1][2], acc[mt][2 * np + 1][3],
                                 a[mt][0], a[mt][1], a[mt][2], a[mt][3], b2, b3);
                    }
                }
            }
        }
    }

#pragma unroll
    for (int mt = 0; mt < 4; mt++) {
        int r0 = m0 + warp_m * 64 + mt * 16 + (lane >> 2);
        float* C0 = g_nbh + (size_t)r0 * H1_;
        float* C1 = C0 + 8 * H1_;
#pragma unroll
        for (int nt = 0; nt < 8; nt++) {
            int col = warp_n * 64 + nt * 8 + (lane & 3) * 2;
            float2 bv = *(const float2*)(bias + col);
            float2 o0, o1;
            o0.x = acc[mt][nt][0] + bv.x; o0.y = acc[mt][nt][1] + bv.y;
            o1.x = acc[mt][nt][2] + bv.x; o1.y = acc[mt][nt][3] + bv.y;
            *(float2*)(C0 + col) = o0;
            *(float2*)(C1 + col) = o1;
        }
    }
}

// ---------------- attention layer 1 (float4 score pass) ----------------
__global__ void __launch_bounds__(256) attn1_kernel(
    const float* __restrict__ x, const float* __restrict__ a12)
{
    int b = blockIdx.x, tid = threadIdx.x, lane = tid & 31, warp = tid >> 5;
    __shared__ __align__(16) float s_a12[256];
    __shared__ float s_sc[64];
    __shared__ float s_red[32];
    __shared__ float s_sx;

    s_a12[tid] = a12[tid];

    // self score: sign(x[b]) . u1 + c1
    float p = 0.f;
#pragma unroll
    for (int i = 0; i < 4; i++) {
        int f = tid + i * 256;
        float v = x[(size_t)b * F_ + f];
        v = v / fmaxf(fabsf(v), 1e-12f);
        p += v * g_u1[f];
    }
    float sx = blockReduce(p, s_red);
    if (tid == 0) s_sx = sx + g_c1;
    __syncthreads();

    const float* base = g_nbh + (size_t)b * N_ * H1_;
    const float4* a4 = (const float4*)s_a12;
    float4 aa = a4[lane], ab = a4[lane + 32];
    float lsum = 0.f, lsq = 0.f;
#pragma unroll
    for (int nn = 0; nn < 8; nn++) {
        int n = warp * 8 + nn;
        const float4* row4 = (const float4*)(base + n * H1_);
        float4 va = row4[lane], vb = row4[lane + 32];
        float d = va.x * aa.x + va.y * aa.y + va.z * aa.z + va.w * aa.w
                + vb.x * ab.x + vb.y * ab.y + vb.z * ab.z + vb.w * ab.w;
        lsum += (va.x + va.y + va.z + va.w) + (vb.x + vb.y + vb.z + vb.w);
        lsq  += (va.x * va.x + va.y * va.y + va.z * va.z + va.w * va.w)
              + (vb.x * vb.x + vb.y * vb.y + vb.z * vb.z + vb.w * vb.w);
        d = warpSum(d);
        if (lane == 0) s_sc[n] = d;
    }
    __syncthreads();

    if (warp == 0) {
        float c = s_sx;
        float v0 = c + s_sc[lane];      v0 = v0 > 0.f ? v0 : ALPHA_ * v0;
        float v1 = c + s_sc[lane + 32]; v1 = v1 > 0.f ? v1 : ALPHA_ * v1;
        float m = fmaxf(v0, v1);
#pragma unroll
        for (int o = 16; o; o >>= 1) m = fmaxf(m, __shfl_xor_sync(0xffffffffu, m, o));
        float e0 = expf(v0 - m), e1 = expf(v1 - m);
        float s = e0 + e1;
#pragma unroll
        for (int o = 16; o; o >>= 1) s += __shfl_xor_sync(0xffffffffu, s, o);
        float inv = 1.f / s;
        s_sc[lane] = e0 * inv; s_sc[lane + 32] = e1 * inv;
    }
    __syncthreads();

    float out = 0.f;
#pragma unroll
    for (int n = 0; n < N_; n++) out += s_sc[n] * base[n * H1_ + tid];
    g_x1[(size_t)b * H1_ + tid] = out;

    float S  = blockReduce(lsum, s_red);
    float S2 = blockReduce(lsq, s_red);
    if (tid == 0) {
        float mean = S * (1.f / 16384.f);
        float var  = S2 * (1.f / 16384.f) - mean * mean;
        g_nbmean[b] = mean;
        g_nbrstd[b] = rsqrtf(var + EPS_);
    }
    float So  = blockReduce(out, s_red);
    float So2 = blockReduce(out * out, s_red);
    if (tid == 0) { atomicAdd(&g_acc[0], So); atomicAdd(&g_acc[1], So2); }
}

// ---------------- fused layer-2: scores + softmax + aggregate + W2 projection ----------
// Replaces gemm2 + attn2 + xc2 + fin1 entirely (GEMM pushed past the attention sum
// by linearity; softmax weights only need nbh . (W2^T a22)).
__global__ void __launch_bounds__(256) attn2f_kernel(
    const float* __restrict__ W2, const float* __restrict__ b2,
    const float* __restrict__ g1p, const float* __restrict__ be1p)
{
    int b = blockIdx.x, tid = threadIdx.x, lane = tid & 31, warp = tid >> 5;
    __shared__ __align__(16) float s_u2b[256];
    __shared__ __align__(16) float s_agg[256];
    __shared__ float s_sc[64];
    __shared__ float s_red[32];
    __shared__ float s_cb;

    s_u2b[tid] = g_u2b[tid];
    float g1 = *g1p, be1 = *be1p;

    // global BN1 stats (inline fin1)
    float inv1 = 1.f / (float)(B_ * H1_);
    float m1 = g_acc[0] * inv1;
    float r1 = rsqrtf(g_acc[1] * inv1 - m1 * m1 + EPS_);

    // self score: bnrelu_global(x1[b]) . u2 + c2
    {
        float v = g_x1[(size_t)b * H1_ + tid];
        float xb = fmaxf(g1 * (v - m1) * r1 + be1, 0.f);
        float S = blockReduce(xb * g_u2[tid], s_red);
        if (tid == 0) s_cb = S + g_c2;
    }

    // per-sample neighbor BN params
    float mn = g_nbmean[b], rs = g_nbrstd[b];
    float sg = g1 * rs;                 // bnrelu(v) = max(sg*(v-mn)+be1, 0)
    float sb2 = be1 - sg * mn;          //            = max(sg*v + sb2, 0)

    const float* base = g_nbh + (size_t)b * N_ * H1_;
    const float4* u4 = (const float4*)s_u2b;
    float4 ua = u4[lane], ub = u4[lane + 32];

    // pass 1: neighbor scores
#pragma unroll
    for (int nn = 0; nn < 8; nn++) {
        int n = warp * 8 + nn;
        const float4* row4 = (const float4*)(base + n * H1_);
        float4 va = row4[lane], vb = row4[lane + 32];
        va.x = fmaxf(sg * va.x + sb2, 0.f); va.y = fmaxf(sg * va.y + sb2, 0.f);
        va.z = fmaxf(sg * va.z + sb2, 0.f); va.w = fmaxf(sg * va.w + sb2, 0.f);
        vb.x = fmaxf(sg * vb.x + sb2, 0.f); vb.y = fmaxf(sg * vb.y + sb2, 0.f);
        vb.z = fmaxf(sg * vb.z + sb2, 0.f); vb.w = fmaxf(sg * vb.w + sb2, 0.f);
        float d = va.x * ua.x + va.y * ua.y + va.z * ua.z + va.w * ua.w
                + vb.x * ub.x + vb.y * ub.y + vb.z * ub.z + vb.w * ub.w;
        d = warpSum(d);
        if (lane == 0) s_sc[n] = d;
    }
    __syncthreads();

    // softmax(leakyrelu(cb + c2b + s_n)) over n
    if (warp == 0) {
        float c = s_cb + g_c2b;
        float v0 = c + s_sc[lane];      v0 = v0 > 0.f ? v0 : ALPHA_ * v0;
        float v1 = c + s_sc[lane + 32]; v1 = v1 > 0.f ? v1 : ALPHA_ * v1;
        float m = fmaxf(v0, v1);
#pragma unroll
        for (int o = 16; o; o >>= 1) m = fmaxf(m, __shfl_xor_sync(0xffffffffu, m, o));
        float e0 = expf(v0 - m), e1 = expf(v1 - m);
        float s = e0 + e1;
#pragma unroll
        for (int o = 16; o; o >>= 1) s += __shfl_xor_sync(0xffffffffu, s, o);
        float inv = 1.f / s;
        s_sc[lane] = e0 * inv; s_sc[lane + 32] = e1 * inv;
    }
    __syncthreads();

    // pass 2: aggregate bnrelu'd neighbors (L2-resident rereads)
    {
        float out = 0.f;
#pragma unroll
        for (int n = 0; n < N_; n++) {
            float v = base[n * H1_ + tid];
            out += s_sc[n] * fmaxf(sg * v + sb2, 0.f);
        }
        s_agg[tid] = out;
    }
    __syncthreads();

    // tiny projection: x2[b,c] = agg . W2[c,:] + b2[c]  (threads 0..127)
    float xv = 0.f;
    if (tid < H2_) {
        const float4* w4 = (const float4*)(W2 + (size_t)tid * H1_);
        const float4* a4 = (const float4*)s_agg;
        float acc = 0.f;
#pragma unroll
        for (int h = 0; h < 64; h++) {
            float4 w = w4[h], a = a4[h];
            acc += w.x * a.x + w.y * a.y + w.z * a.z + w.w * a.w;
        }
        xv = acc + b2[tid];
        g_x2[(size_t)b * H2_ + tid] = xv;
    }
    // BN2 global stats
    float S  = blockReduce(tid < H2_ ? xv : 0.f, s_red);
    float S2 = blockReduce(tid < H2_ ? xv * xv : 0.f, s_red);
    if (tid == 0) { atomicAdd(&g_acc[2], S); atomicAdd(&g_acc[3], S2); }
}

// ---------------- final BN + classifier (BN2 stats inline) ----------------
__global__ void __launch_bounds__(128) logits_kernel(
    const float* __restrict__ Wl, const float* __restrict__ bl,
    const float* __restrict__ g2p, const float* __restrict__ be2p,
    float* __restrict__ out)
{
    int b = blockIdx.x, tid = threadIdx.x, lane = tid & 31, warp = tid >> 5;
    __shared__ __align__(16) float s_x[128];
    float inv2 = 1.f / (float)(B_ * H2_);
    float m2 = g_acc[2] * inv2;
    float r2 = rsqrtf(g_acc[3] * inv2 - m2 * m2 + EPS_);
    float g = *g2p, be = *be2p;
    float v = g_x2[(size_t)b * H2_ + tid];
    s_x[tid] = fmaxf(g * (v - m2) * r2 + be, 0.f);
    __syncthreads();
    float4 xv = *(const float4*)&s_x[lane * 4];
#pragma unroll
    for (int cc = 0; cc < 32; cc++) {
        int c = warp * 32 + cc;
        float4 wv = *(const float4*)(Wl + (size_t)c * H2_ + lane * 4);
        float d = wv.x * xv.x + wv.y * xv.y + wv.z * xv.z + wv.w * xv.w;
        d = warpSum(d);
        if (lane == 0) out[(size_t)b * NC_ + c] = d + bl[c];
    }
}

// ---------------- launch ----------------
extern "C" void kernel_launch(void* const* d_in, const int* in_sizes, int n_in,
                              void* d_out, int out_size) {
    (void)in_sizes; (void)n_in; (void)out_size;
    const float* x   = (const float*)d_in[0];
    const float* nb  = (const float*)d_in[1];
    const float* W1  = (const float*)d_in[2];
    const float* b1  = (const float*)d_in[3];
    const float* a11 = (const float*)d_in[4];
    const float* a12 = (const float*)d_in[5];
    const float* g1  = (const float*)d_in[6];
    const float* be1 = (const float*)d_in[7];
    const float* W2  = (const float*)d_in[8];
    const float* b2  = (const float*)d_in[9];
    const float* a21 = (const float*)d_in[10];
    const float* a22 = (const float*)d_in[11];
    const float* g2  = (const float*)d_in[12];
    const float* be2 = (const float*)d_in[13];
    const float* Wl  = (const float*)d_in[14];
    const float* bl  = (const float*)d_in[15];
    float* out = (float*)d_out;

    cudaFuncSetAttribute(tc_gemm1, cudaFuncAttributeMaxDynamicSharedMemorySize, SM_TOTAL);

    pre_kernel<<<6, 256>>>(W1, a11, b1, W2, a21, a22, b2);
    wsplit_kernel<<<H1_, 256>>>(W1);
    tc_gemm1<<<512, 256, SM_TOTAL>>>(nb, b1);
    attn1_kernel<<<B_, 256>>>(x, a12);
    attn2f_kernel<<<B_, 256>>>(W2, b2, g1, be1);
    logits_kernel<<<B_, 128>>>(Wl, bl, g2, be2, out);
}